// round 6
// baseline (speedup 1.0000x reference)
#include <cuda_runtime.h>
#include <cstdint>

// GRU-D diagonal recurrence. R6: TWO chains per thread (float2 over adjacent
// features) for 2x ILP in the serial h-chain + 64-bit loads/stores.
// Pipeline schedule identical to R5 (depth-2, period-3 slot rotation).

#define TT 512
#define BB 256
#define FF 256
#define BF (BB * FF)
#define F2 (FF / 2)            // float2 elements per row: 128
#define BF2 (BF / 2)           // float2 elements per timestep: 32768
#define UNROLL 8
#define NBATCH (TT / UNROLL)   // 64
#define BLK 64

__device__ __forceinline__ float tanh_approx(float v) {
    float r;
    asm("tanh.approx.f32 %0, %1;" : "=f"(r) : "f"(v));
    return r;
}
__device__ __forceinline__ float ex2_f(float v) {
    float r;
    asm("ex2.approx.f32 %0, %1;" : "=f"(r) : "f"(v));
    return r;
}

__global__ void __launch_bounds__(BLK) grud_kernel(
    const float2* __restrict__ X,
    const float2* __restrict__ Mask,
    const float2* __restrict__ Delta,
    const float2* __restrict__ x_mean,
    const float2* __restrict__ w_dg_x, const float2* __restrict__ b_dg_x,
    const float2* __restrict__ w_dg_h, const float2* __restrict__ b_dg_h,
    const float2* __restrict__ w_xz,  const float2* __restrict__ u_hz, const float2* __restrict__ b_z,
    const float2* __restrict__ w_xr,  const float2* __restrict__ u_hr, const float2* __restrict__ b_r,
    const float2* __restrict__ w_xh,  const float2* __restrict__ u_hh,
    const float2* __restrict__ v_mh,  const float2* __restrict__ b_h,
    float2* __restrict__ out,        // [B, T, F] as float2
    float2* __restrict__ out_last)   // [B, F] as float2, or nullptr
{
    const int tid = blockIdx.x * BLK + threadIdx.x;   // 0..32767
    const int f2 = tid & (F2 - 1);                    // float2 feature index
    const int b  = tid >> 7;

    const float LOG2E = 1.4426950408889634f;

    // Per-feature params for both lanes, constants folded in.
    float2 t2;
    const float2 xm = x_mean[f2];
    t2 = w_dg_x[f2]; const float nwdgx0 = -LOG2E * t2.x, nwdgx1 = -LOG2E * t2.y;
    t2 = b_dg_x[f2]; const float nbdgx0 = -LOG2E * t2.x, nbdgx1 = -LOG2E * t2.y;
    t2 = w_dg_h[f2]; const float nwdgh0 = -LOG2E * t2.x, nwdgh1 = -LOG2E * t2.y;
    t2 = b_dg_h[f2]; const float nbdgh0 = -LOG2E * t2.x, nbdgh1 = -LOG2E * t2.y;
    t2 = w_xz[f2];   const float wxz0 = 0.5f * t2.x, wxz1 = 0.5f * t2.y;
    t2 = u_hz[f2];   const float uhz0 = 0.5f * t2.x, uhz1 = 0.5f * t2.y;
    t2 = b_z[f2];    const float bz0  = 0.5f * t2.x, bz1  = 0.5f * t2.y;
    t2 = w_xr[f2];   const float wxr0 = 0.5f * t2.x, wxr1 = 0.5f * t2.y;
    t2 = u_hr[f2];   const float uhr0 = 0.5f * t2.x, uhr1 = 0.5f * t2.y;
    t2 = b_r[f2];    const float br0  = 0.5f * t2.x, br1  = 0.5f * t2.y;
    const float2 wxh = w_xh[f2], uhh = u_hh[f2];
    const float2 vmh = v_mh[f2], bh  = b_h[f2];

    const float2* xp = X     + (size_t)b * F2 + f2;   // [T,B,F]: t-stride = BF2
    const float2* mp = Mask  + (size_t)b * F2 + f2;
    const float2* dp = Delta + (size_t)b * F2 + f2;
    float2*       op = out   + (size_t)b * TT * F2 + f2;  // [B,T,F]: t-stride = F2

    float h0 = 0.0f, h1 = 0.0f;

    float2 xv[3][UNROLL], mv[3][UNROLL], dv[3][UNROLL];

    auto load_batch = [&](int n, int s) {
        const float2* xq = xp + (size_t)n * (BF2 * UNROLL);
        const float2* mq = mp + (size_t)n * (BF2 * UNROLL);
        const float2* dq = dp + (size_t)n * (BF2 * UNROLL);
        #pragma unroll
        for (int u = 0; u < UNROLL; ++u) {
            xv[s][u] = __ldcs(xq + u * BF2);
            mv[s][u] = __ldcs(mq + u * BF2);
            dv[s][u] = __ldcs(dq + u * BF2);
        }
    };

    auto compute_batch = [&](int n, int s) {
        float2* oq = op + (size_t)n * (F2 * UNROLL);
        #pragma unroll
        for (int u = 0; u < UNROLL; ++u) {
            float x0 = xv[s][u].x, x1 = xv[s][u].y;
            float m0 = mv[s][u].x, m1 = mv[s][u].y;
            float d0 = dv[s][u].x, d1 = dv[s][u].y;

            // gammas: ex2(min(0, fma(nw,d,nb)))
            float gx0 = ex2_f(fminf(0.0f, fmaf(nwdgx0, d0, nbdgx0)));
            float gx1 = ex2_f(fminf(0.0f, fmaf(nwdgx1, d1, nbdgx1)));
            float gh0 = ex2_f(fminf(0.0f, fmaf(nwdgh0, d0, nbdgh0)));
            float gh1 = ex2_f(fminf(0.0f, fmaf(nwdgh1, d1, nbdgh1)));

            // x imputation
            float xi0 = fmaf(gx0, x0, (1.0f - gx0) * xm.x);
            float xi1 = fmaf(gx1, x1, (1.0f - gx1) * xm.y);
            x0 = fmaf(m0, x0, (1.0f - m0) * xi0);
            x1 = fmaf(m1, x1, (1.0f - m1) * xi1);

            // h-independent partials
            float pz0 = fmaf(wxz0, x0, bz0);
            float pz1 = fmaf(wxz1, x1, bz1);
            float pr0 = fmaf(wxr0, x0, br0);
            float pr1 = fmaf(wxr1, x1, br1);
            float ph0 = fmaf(wxh.x, x0, fmaf(vmh.x, m0, bh.x));
            float ph1 = fmaf(wxh.y, x1, fmaf(vmh.y, m1, bh.y));

            h0 = gh0 * h0;
            h1 = gh1 * h1;

            float z0 = fmaf(0.5f, tanh_approx(fmaf(uhz0, h0, pz0)), 0.5f);
            float z1 = fmaf(0.5f, tanh_approx(fmaf(uhz1, h1, pz1)), 0.5f);
            float r0 = fmaf(0.5f, tanh_approx(fmaf(uhr0, h0, pr0)), 0.5f);
            float r1 = fmaf(0.5f, tanh_approx(fmaf(uhr1, h1, pr1)), 0.5f);
            float ht0 = tanh_approx(fmaf(uhh.x, r0 * h0, ph0));
            float ht1 = tanh_approx(fmaf(uhh.y, r1 * h1, ph1));

            h0 = fmaf(z0, ht0 - h0, h0);
            h1 = fmaf(z1, ht1 - h1, h1);

            float2 hv; hv.x = h0; hv.y = h1;
            __stcs(oq + u * F2, hv);
        }
    };

    // Depth-2 pipeline, period-3 slot rotation via x3-unrolled loop (R5-proven).
    load_batch(0, 0);
    load_batch(1, 1);

    #pragma unroll 1
    for (int n = 0; n < NBATCH - 1; n += 3) {
        load_batch(n + 2, 2);
        compute_batch(n, 0);
        if (n + 3 < NBATCH) load_batch(n + 3, 0);
        compute_batch(n + 1, 1);
        if (n + 4 < NBATCH) load_batch(n + 4, 1);
        compute_batch(n + 2, 2);
    }
    compute_batch(NBATCH - 1, 0);   // batch 63 sits in slot0 (loaded at n=60)

    if (out_last != nullptr) {
        float2 hv; hv.x = h0; hv.y = h1;
        out_last[(size_t)b * F2 + f2] = hv;
    }
}

extern "C" void kernel_launch(void* const* d_in, const int* in_sizes, int n_in,
                              void* d_out, int out_size) {
    const float2* X      = (const float2*)d_in[0];
    const float2* Mask   = (const float2*)d_in[1];
    const float2* Delta  = (const float2*)d_in[2];
    const float2* x_mean = (const float2*)d_in[3];
    const float2* w_dg_x = (const float2*)d_in[4];
    const float2* b_dg_x = (const float2*)d_in[5];
    const float2* w_dg_h = (const float2*)d_in[6];
    const float2* b_dg_h = (const float2*)d_in[7];
    const float2* w_xz   = (const float2*)d_in[8];
    const float2* u_hz   = (const float2*)d_in[9];
    const float2* b_z    = (const float2*)d_in[10];
    const float2* w_xr   = (const float2*)d_in[11];
    const float2* u_hr   = (const float2*)d_in[12];
    const float2* b_r    = (const float2*)d_in[13];
    const float2* w_xh   = (const float2*)d_in[14];
    const float2* u_hh   = (const float2*)d_in[15];
    const float2* v_mh   = (const float2*)d_in[16];
    const float2* b_h    = (const float2*)d_in[17];

    float2* out = (float2*)d_out;
    const long long hs_elems = (long long)BB * TT * FF;   // in floats
    float2* out_last = ((long long)out_size >= hs_elems + (long long)BB * FF)
                           ? out + hs_elems / 2 : nullptr;

    const int nthreads = BF / 2;   // 32768 threads, 2 chains each
    grud_kernel<<<nthreads / BLK, BLK>>>(X, Mask, Delta, x_mean,
                                         w_dg_x, b_dg_x, w_dg_h, b_dg_h,
                                         w_xz, u_hz, b_z,
                                         w_xr, u_hr, b_r,
                                         w_xh, u_hh, v_mh, b_h,
                                         out, out_last);
}

// round 7
// speedup vs baseline: 1.2308x; 1.2308x over previous
#include <cuda_runtime.h>
#include <cstdint>

// GRU-D diagonal recurrence. One thread = one (b,f) chain, T=512 steps.
// R7: back to R5 operating point (2048 warps). Branch-free main loop
// (tail peeled), cheaper x-imputation. Depth-2 pipeline, period-3 slots.

#define TT 512
#define BB 256
#define FF 256
#define BF (BB * FF)
#define UNROLL 8
#define NBATCH (TT / UNROLL)   // 64
#define BLK 64

__device__ __forceinline__ float tanh_approx(float v) {
    float r;
    asm("tanh.approx.f32 %0, %1;" : "=f"(r) : "f"(v));
    return r;
}
__device__ __forceinline__ float ex2_f(float v) {
    float r;
    asm("ex2.approx.f32 %0, %1;" : "=f"(r) : "f"(v));
    return r;
}

__global__ void __launch_bounds__(BLK) grud_kernel(
    const float* __restrict__ X,
    const float* __restrict__ Mask,
    const float* __restrict__ Delta,
    const float* __restrict__ x_mean,
    const float* __restrict__ w_dg_x, const float* __restrict__ b_dg_x,
    const float* __restrict__ w_dg_h, const float* __restrict__ b_dg_h,
    const float* __restrict__ w_xz,  const float* __restrict__ u_hz, const float* __restrict__ b_z,
    const float* __restrict__ w_xr,  const float* __restrict__ u_hr, const float* __restrict__ b_r,
    const float* __restrict__ w_xh,  const float* __restrict__ u_hh,
    const float* __restrict__ v_mh,  const float* __restrict__ b_h,
    float* __restrict__ out,        // [B, T, F]
    float* __restrict__ out_last)   // [B, F] or nullptr
{
    const int tid = blockIdx.x * BLK + threadIdx.x;
    const int f = tid & (FF - 1);
    const int b = tid >> 8;

    const float LOG2E = 1.4426950408889634f;

    const float xm    = x_mean[f];
    const float nwdgx = -LOG2E * w_dg_x[f], nbdgx = -LOG2E * b_dg_x[f];
    const float nwdgh = -LOG2E * w_dg_h[f], nbdgh = -LOG2E * b_dg_h[f];
    const float wxz2  = 0.5f * w_xz[f], uhz2 = 0.5f * u_hz[f], bz2 = 0.5f * b_z[f];
    const float wxr2  = 0.5f * w_xr[f], uhr2 = 0.5f * u_hr[f], br2 = 0.5f * b_r[f];
    const float wxh   = w_xh[f], uhh = u_hh[f];
    const float vmh   = v_mh[f], bh  = b_h[f];

    const float* xp = X     + (size_t)b * FF + f;       // [T,B,F]: t-stride BF
    const float* mp = Mask  + (size_t)b * FF + f;
    const float* dp = Delta + (size_t)b * FF + f;
    float*       op = out   + (size_t)b * TT * FF + f;  // [B,T,F]: t-stride FF

    float h = 0.0f;

    float xv[3][UNROLL], mv[3][UNROLL], dv[3][UNROLL];

    auto load_batch = [&](int n, int s) {
        const float* xq = xp + (size_t)n * (BF * UNROLL);
        const float* mq = mp + (size_t)n * (BF * UNROLL);
        const float* dq = dp + (size_t)n * (BF * UNROLL);
        #pragma unroll
        for (int u = 0; u < UNROLL; ++u) {
            xv[s][u] = __ldcs(xq + u * BF);
            mv[s][u] = __ldcs(mq + u * BF);
            dv[s][u] = __ldcs(dq + u * BF);
        }
    };
    auto compute_batch = [&](int n, int s) {
        float* oq = op + (size_t)n * (FF * UNROLL);
        #pragma unroll
        for (int u = 0; u < UNROLL; ++u) {
            float x = xv[s][u], m = mv[s][u], d = dv[s][u];

            // gamma = exp(-relu(w*d+b)) = ex2(min(0, fma(nw, d, nb)))
            float gx = ex2_f(fminf(0.0f, fmaf(nwdgx, d, nbdgx)));
            float gh = ex2_f(fminf(0.0f, fmaf(nwdgh, d, nbdgh)));

            // x' = x + (1-m)*(xi - x),  xi = xm + gx*(x - xm)
            float xi = fmaf(gx, x - xm, xm);
            x = fmaf(1.0f - m, xi - x, x);

            // h-independent partials
            float pz = fmaf(wxz2, x, bz2);
            float pr = fmaf(wxr2, x, br2);
            float ph = fmaf(wxh, x, fmaf(vmh, m, bh));

            h = gh * h;

            float z  = fmaf(0.5f, tanh_approx(fmaf(uhz2, h, pz)), 0.5f);
            float r  = fmaf(0.5f, tanh_approx(fmaf(uhr2, h, pr)), 0.5f);
            float ht = tanh_approx(fmaf(uhh, r * h, ph));

            h = fmaf(z, ht - h, h);

            __stcs(oq + u * FF, h);
        }
    };

    // Depth-2 pipeline, period-3 rotation. Main loop is branch-free; the
    // last 4 batches are peeled.
    load_batch(0, 0);
    load_batch(1, 1);

    #pragma unroll 1
    for (int n = 0; n <= NBATCH - 7; n += 3) {   // n = 0,3,...,57
        load_batch(n + 2, 2);
        compute_batch(n, 0);
        load_batch(n + 3, 0);
        compute_batch(n + 1, 1);
        load_batch(n + 4, 1);
        compute_batch(n + 2, 2);
    }
    // After n=57 iteration: computed 0..59; batch 60 in slot0, 61 in slot1.
    load_batch(62, 2);
    compute_batch(60, 0);
    load_batch(63, 0);
    compute_batch(61, 1);
    compute_batch(62, 2);
    compute_batch(63, 0);

    if (out_last != nullptr) {
        out_last[(size_t)b * FF + f] = h;
    }
}

extern "C" void kernel_launch(void* const* d_in, const int* in_sizes, int n_in,
                              void* d_out, int out_size) {
    const float* X      = (const float*)d_in[0];
    const float* Mask   = (const float*)d_in[1];
    const float* Delta  = (const float*)d_in[2];
    const float* x_mean = (const float*)d_in[3];
    const float* w_dg_x = (const float*)d_in[4];
    const float* b_dg_x = (const float*)d_in[5];
    const float* w_dg_h = (const float*)d_in[6];
    const float* b_dg_h = (const float*)d_in[7];
    const float* w_xz   = (const float*)d_in[8];
    const float* u_hz   = (const float*)d_in[9];
    const float* b_z    = (const float*)d_in[10];
    const float* w_xr   = (const float*)d_in[11];
    const float* u_hr   = (const float*)d_in[12];
    const float* b_r    = (const float*)d_in[13];
    const float* w_xh   = (const float*)d_in[14];
    const float* u_hh   = (const float*)d_in[15];
    const float* v_mh   = (const float*)d_in[16];
    const float* b_h    = (const float*)d_in[17];

    float* out = (float*)d_out;
    const long long hs_elems = (long long)BB * TT * FF;
    float* out_last = ((long long)out_size >= hs_elems + (long long)BB * FF)
                          ? out + hs_elems : nullptr;

    grud_kernel<<<BF / BLK, BLK>>>(X, Mask, Delta, x_mean,
                                   w_dg_x, b_dg_x, w_dg_h, b_dg_h,
                                   w_xz, u_hz, b_z,
                                   w_xr, u_hr, b_r,
                                   w_xh, u_hh, v_mh, b_h,
                                   out, out_last);
}